// round 3
// baseline (speedup 1.0000x reference)
#include <cuda_runtime.h>
#include <math.h>

// Problem constants
#define B 256
#define T 96
#define F 368
#define H 368
#define G3 1104          // 3*H
#define NC 29
#define OUT_NMS_OFF   (B*T)          // 24576
#define OUT_FINE_OFF  (B*T + B*T*2)  // 73728

// Recurrence persistent-kernel config
#define NCOLBLK 74
#define COLS_PER_BLK 5      // last block has 3
#define GRID_REC 148        // 2 batch-halves * 74 col-blocks, all resident
#define THR_REC 512

// ---------------- device scratch ----------------
__device__ float g_xprojT[(size_t)T * G3 * B];      // (t, g, b)
__device__ float g_temporal[(size_t)T * B * H];     // (t, b, h)
__device__ float g_scores[(size_t)B * T * 2];
__device__ unsigned g_barrier;

// ---------------- Kernel 1: xproj = feat @ Wi^T + bi, transposed output ----------------
#define BM 128
#define BN 64
#define BK 16
__global__ __launch_bounds__(256) void xproj_gemm(const float* __restrict__ feat,
                                                  const float* __restrict__ Wi,
                                                  const float* __restrict__ bi) {
    __shared__ float As[BK][BM];
    __shared__ float Ws[BK][BN];
    const int bm = blockIdx.x * BM;
    const int bn = blockIdx.y * BN;
    const int tid = threadIdx.x;
    const int tx = tid % 16;
    const int ty = tid / 16;

    float acc[8][4];
#pragma unroll
    for (int i = 0; i < 8; i++)
#pragma unroll
        for (int j = 0; j < 4; j++) acc[i][j] = 0.f;

    for (int kt = 0; kt < F; kt += BK) {
#pragma unroll
        for (int l = 0; l < 2; l++) {
            int idx = tid + l * 256;
            int m = idx >> 2;
            int kq = idx & 3;
            float4 v = *(const float4*)(feat + (size_t)(bm + m) * F + kt + kq * 4);
            As[kq * 4 + 0][m] = v.x;
            As[kq * 4 + 1][m] = v.y;
            As[kq * 4 + 2][m] = v.z;
            As[kq * 4 + 3][m] = v.w;
        }
        {
            int m = tid >> 2;
            int kq = tid & 3;
            int g = bn + m;
            float4 v = make_float4(0.f, 0.f, 0.f, 0.f);
            if (g < G3) v = *(const float4*)(Wi + (size_t)g * F + kt + kq * 4);
            Ws[kq * 4 + 0][m] = v.x;
            Ws[kq * 4 + 1][m] = v.y;
            Ws[kq * 4 + 2][m] = v.z;
            Ws[kq * 4 + 3][m] = v.w;
        }
        __syncthreads();
#pragma unroll
        for (int k = 0; k < BK; k++) {
            float a[8], w[4];
            *(float4*)(a)     = *(const float4*)&As[k][ty * 8];
            *(float4*)(a + 4) = *(const float4*)&As[k][ty * 8 + 4];
            *(float4*)(w)     = *(const float4*)&Ws[k][tx * 4];
#pragma unroll
            for (int i = 0; i < 8; i++)
#pragma unroll
                for (int j = 0; j < 4; j++) acc[i][j] = fmaf(a[i], w[j], acc[i][j]);
        }
        __syncthreads();
    }
#pragma unroll
    for (int i = 0; i < 8; i++) {
        int m = bm + ty * 8 + i;
        int bb = m / T;
        int tt = m % T;
#pragma unroll
        for (int j = 0; j < 4; j++) {
            int g = bn + tx * 4 + j;
            if (g < G3)
                g_xprojT[((size_t)tt * G3 + g) * B + bb] = acc[i][j] + bi[g];
        }
    }
}

// ---------------- barrier reset (graph replays must start clean) ----------------
__global__ void reset_barrier_kernel() { g_barrier = 0u; }

// ---------------- grid-wide barrier (all GRID_REC blocks resident) ----------------
__device__ __forceinline__ void grid_barrier(unsigned phase) {
    __syncthreads();
    if (threadIdx.x == 0) {
        __threadfence();
        atomicAdd(&g_barrier, 1u);
        const unsigned target = phase * (unsigned)GRID_REC;
        while (*(volatile unsigned*)&g_barrier < target) { }
        __threadfence();
    }
    __syncthreads();
}

// ---------------- persistent GRU recurrence ----------------
template<int MYN>
__device__ __forceinline__ void kloop(float acc[2][3], const float* __restrict__ hrow,
                                      const float* __restrict__ wrow0,
                                      const float* __restrict__ wrow1) {
    const float* wr[2] = { wrow0, wrow1 };
#pragma unroll 2
    for (int k4 = 0; k4 < H / 4; k4++) {
        float4 hv = *(const float4*)(hrow + k4 * 4);
#pragma unroll
        for (int c = 0; c < MYN; c++) {
#pragma unroll
            for (int g = 0; g < 3; g++) {
                float4 wv = *(const float4*)(wr[c] + (size_t)g * H + k4 * 4);
                acc[c][g] = fmaf(hv.x, wv.x, acc[c][g]);
                acc[c][g] = fmaf(hv.y, wv.y, acc[c][g]);
                acc[c][g] = fmaf(hv.z, wv.z, acc[c][g]);
                acc[c][g] = fmaf(hv.w, wv.w, acc[c][g]);
            }
        }
    }
}

__global__ __launch_bounds__(THR_REC) void gru_persistent(const float* __restrict__ Wh,
                                                          const float* __restrict__ bhb) {
    __shared__ float ws[15 * H];   // up to 5 cols * 3 gates, 22 KB, lives all 96 steps
    const int tid = threadIdx.x;
    const int bh = blockIdx.x & 1;          // batch half
    const int cb = blockIdx.x >> 1;         // col block 0..73
    const int j0 = cb * COLS_PER_BLK;
    const int ncols_blk = (cb == NCOLBLK - 1) ? (H - j0) : COLS_PER_BLK;  // 5 or 3
    const int nrows_blk = ncols_blk * 3;
    const int cg = tid >> 7;                // 0..3 col-group
    const int b  = bh * 128 + (tid & 127);

    // Load this block's Wh slice into SMEM once (rows: jj*3+g -> Wh[g*H + j0+jj])
    for (int q = tid; q < nrows_blk * (H / 4); q += THR_REC) {
        int row = q / (H / 4);
        int kq  = q % (H / 4);
        int jj = row / 3, g = row % 3;
        *(float4*)&ws[(size_t)row * H + kq * 4] =
            *(const float4*)(Wh + (size_t)(g * H + j0 + jj) * H + kq * 4);
    }
    __syncthreads();

    // column assignment per col-group: 5 cols -> cg0:{0,4} cg1:{1} cg2:{2} cg3:{3}
    //                                  3 cols -> cg0:{0} cg1:{1} cg2:{2} cg3:{}
    int mycols[2]; int myn = 0;
    if (cg < ncols_blk) mycols[myn++] = cg;
    if (cg == 0 && ncols_blk == 5) mycols[myn++] = 4;
    if (myn == 0) mycols[0] = 0;
    if (myn < 2) mycols[1] = mycols[0];

    const float* wrow0 = ws + (size_t)(mycols[0] * 3) * H;
    const float* wrow1 = ws + (size_t)(mycols[1] * 3) * H;

    float bias[2][3];
#pragma unroll
    for (int c = 0; c < 2; c++)
#pragma unroll
        for (int g = 0; g < 3; g++)
            bias[c][g] = bhb[g * H + j0 + mycols[c]];

    for (int t = 0; t < T; t++) {
        float acc[2][3];
#pragma unroll
        for (int c = 0; c < 2; c++)
#pragma unroll
            for (int g = 0; g < 3; g++) acc[c][g] = bias[c][g];

        const float* hprev = g_temporal + ((size_t)(t - 1) * B + b) * H;
        if (t > 0 && myn > 0) {
            if (myn == 2) kloop<2>(acc, hprev, wrow0, wrow1);
            else          kloop<1>(acc, hprev, wrow0, wrow1);
        }

        if (myn > 0) {
            const float* xp = g_xprojT + (size_t)t * G3 * B;
            float* hout = g_temporal + ((size_t)t * B + b) * H;
#pragma unroll
            for (int c = 0; c < 2; c++) {
                if (c >= myn) break;
                int j = j0 + mycols[c];
                float gi_r = xp[((size_t)(0 * H + j)) * B + b];
                float gi_z = xp[((size_t)(1 * H + j)) * B + b];
                float gi_n = xp[((size_t)(2 * H + j)) * B + b];
                float r = 1.f / (1.f + expf(-(gi_r + acc[c][0])));
                float z = 1.f / (1.f + expf(-(gi_z + acc[c][1])));
                float n = tanhf(gi_n + r * acc[c][2]);
                float hp = (t > 0) ? hprev[j] : 0.f;
                hout[j] = (1.f - z) * n + z * hp;
            }
        }

        if (t < T - 1) grid_barrier((unsigned)(t + 1));
    }
}

// ---------------- Kernel 3: heads ----------------
__global__ __launch_bounds__(256) void heads_kernel(const float* __restrict__ Wc,
                                                    const float* __restrict__ bc,
                                                    const float* __restrict__ Wf,
                                                    const float* __restrict__ bf,
                                                    float* __restrict__ out) {
    __shared__ float w[31 * H];
    const int t = blockIdx.x;
    const int tid = threadIdx.x;
    const int b = tid;

    for (int q = tid; q < 31 * (H / 4); q += 256) {
        int row = q / (H / 4);
        int kq = q % (H / 4);
        const float* src = (row < 2) ? (Wc + (size_t)row * H) : (Wf + (size_t)(row - 2) * H);
        *(float4*)&w[(size_t)row * H + kq * 4] = *(const float4*)(src + kq * 4);
    }
    __syncthreads();

    float acc[31];
    acc[0] = bc[0];
    acc[1] = bc[1];
#pragma unroll
    for (int i = 0; i < NC; i++) acc[2 + i] = bf[i];

    const float* hrow = g_temporal + (size_t)t * B * H + (size_t)b * H;
    for (int k4 = 0; k4 < H / 4; k4++) {
        float4 h4 = *(const float4*)(hrow + k4 * 4);
#pragma unroll
        for (int row = 0; row < 31; row++) {
            float4 wv = *(const float4*)&w[(size_t)row * H + k4 * 4];
            acc[row] = fmaf(h4.x, wv.x, acc[row]);
            acc[row] = fmaf(h4.y, wv.y, acc[row]);
            acc[row] = fmaf(h4.z, wv.z, acc[row]);
            acc[row] = fmaf(h4.w, wv.w, acc[row]);
        }
    }

    float l0 = acc[0], l1 = acc[1];
    float m = fmaxf(l0, l1);
    float e0 = expf(l0 - m), e1 = expf(l1 - m);
    float inv = 1.f / (e0 + e1);
    size_t idx = (size_t)b * T + t;
    g_scores[idx * 2 + 0] = e0 * inv;
    g_scores[idx * 2 + 1] = e1 * inv;

    float* fine = out + OUT_FINE_OFF + idx * NC;
#pragma unroll
    for (int i = 0; i < NC; i++) fine[i] = 1.f / (1.f + expf(-acc[2 + i]));
}

// ---------------- Kernel 4: NMS + decisions ----------------
__global__ void nms_kernel(float* __restrict__ out) {
    int idx = blockIdx.x * blockDim.x + threadIdx.x;
    if (idx >= B * T) return;
    int b = idx / T;
    int t = idx % T;
    const float* sb = g_scores + (size_t)b * T * 2;
    float s0 = sb[t * 2 + 0];
    float s1 = sb[t * 2 + 1];
    float wmin = INFINITY;
#pragma unroll
    for (int k = -2; k <= 2; k++) {
        int tt = t + k;
        if (tt >= 0 && tt < T) wmin = fminf(wmin, sb[tt * 2]);
    }
    bool keep = (s0 == wmin);
    float o0 = keep ? s0 : 0.f;
    float o1 = keep ? s1 : 0.f;
    out[idx] = (o1 > o0) ? 1.0f : 0.0f;
    out[OUT_NMS_OFF + (size_t)idx * 2 + 0] = o0;
    out[OUT_NMS_OFF + (size_t)idx * 2 + 1] = o1;
}

// ---------------- launch ----------------
extern "C" void kernel_launch(void* const* d_in, const int* in_sizes, int n_in,
                              void* d_out, int out_size) {
    const float* feat = (const float*)d_in[0];
    const float* Wi  = (const float*)d_in[2];
    const float* Wh  = (const float*)d_in[3];
    const float* bi  = (const float*)d_in[4];
    const float* bhb = (const float*)d_in[5];
    const float* Wc  = (const float*)d_in[6];
    const float* bc  = (const float*)d_in[7];
    const float* Wf  = (const float*)d_in[8];
    const float* bf  = (const float*)d_in[9];
    float* out = (float*)d_out;

    reset_barrier_kernel<<<1, 1>>>();

    dim3 g1((B * T) / BM, (G3 + BN - 1) / BN);
    xproj_gemm<<<g1, 256>>>(feat, Wi, bi);

    gru_persistent<<<GRID_REC, THR_REC>>>(Wh, bhb);

    heads_kernel<<<T, 256>>>(Wc, bc, Wf, bf, out);
    nms_kernel<<<(B * T + 255) / 256, 256>>>(out);
}

// round 5
// speedup vs baseline: 1.2227x; 1.2227x over previous
#include <cuda_runtime.h>
#include <math.h>

// Problem constants
#define B 256
#define T 96
#define F 368
#define H 368
#define G3 1104          // 3*H
#define NC 29
#define OUT_NMS_OFF   (B*T)          // 24576
#define OUT_FINE_OFF  (B*T + B*T*2)  // 73728

// Recurrence persistent-kernel config
#define NCOLBLK 74
#define COLS_PER_BLK 5      // last block has 3
#define GRID_REC 148        // 2 batch-halves * 74 col-blocks, all resident
#define THR_REC 512

// ---------------- device scratch ----------------
__device__ float g_xprojT[(size_t)T * G3 * B];      // (t, g, b)  b contiguous
__device__ float g_temporalT[(size_t)T * H * B];    // (t, k, b)  b contiguous!
__device__ float g_scores[(size_t)B * T * 2];
__device__ unsigned g_barrier;

// ---------------- Kernel 1: xproj = feat @ Wi^T + bi, transposed output ----------------
#define BM 128
#define BN 64
#define BK 16
__global__ __launch_bounds__(256) void xproj_gemm(const float* __restrict__ feat,
                                                  const float* __restrict__ Wi,
                                                  const float* __restrict__ bi) {
    __shared__ float As[BK][BM];
    __shared__ float Ws[BK][BN];
    const int bm = blockIdx.x * BM;
    const int bn = blockIdx.y * BN;
    const int tid = threadIdx.x;
    const int tx = tid % 16;
    const int ty = tid / 16;

    float acc[8][4];
#pragma unroll
    for (int i = 0; i < 8; i++)
#pragma unroll
        for (int j = 0; j < 4; j++) acc[i][j] = 0.f;

    for (int kt = 0; kt < F; kt += BK) {
#pragma unroll
        for (int l = 0; l < 2; l++) {
            int idx = tid + l * 256;
            int m = idx >> 2;
            int kq = idx & 3;
            float4 v = *(const float4*)(feat + (size_t)(bm + m) * F + kt + kq * 4);
            As[kq * 4 + 0][m] = v.x;
            As[kq * 4 + 1][m] = v.y;
            As[kq * 4 + 2][m] = v.z;
            As[kq * 4 + 3][m] = v.w;
        }
        {
            int m = tid >> 2;
            int kq = tid & 3;
            int g = bn + m;
            float4 v = make_float4(0.f, 0.f, 0.f, 0.f);
            if (g < G3) v = *(const float4*)(Wi + (size_t)g * F + kt + kq * 4);
            Ws[kq * 4 + 0][m] = v.x;
            Ws[kq * 4 + 1][m] = v.y;
            Ws[kq * 4 + 2][m] = v.z;
            Ws[kq * 4 + 3][m] = v.w;
        }
        __syncthreads();
#pragma unroll
        for (int k = 0; k < BK; k++) {
            float a[8], w[4];
            *(float4*)(a)     = *(const float4*)&As[k][ty * 8];
            *(float4*)(a + 4) = *(const float4*)&As[k][ty * 8 + 4];
            *(float4*)(w)     = *(const float4*)&Ws[k][tx * 4];
#pragma unroll
            for (int i = 0; i < 8; i++)
#pragma unroll
                for (int j = 0; j < 4; j++) acc[i][j] = fmaf(a[i], w[j], acc[i][j]);
        }
        __syncthreads();
    }
#pragma unroll
    for (int i = 0; i < 8; i++) {
        int m = bm + ty * 8 + i;
        int bb = m / T;
        int tt = m % T;
#pragma unroll
        for (int j = 0; j < 4; j++) {
            int g = bn + tx * 4 + j;
            if (g < G3)
                g_xprojT[((size_t)tt * G3 + g) * B + bb] = acc[i][j] + bi[g];
        }
    }
}

// ---------------- barrier reset ----------------
__global__ void reset_barrier_kernel() { g_barrier = 0u; }

// ---------------- grid-wide barrier ----------------
__device__ __forceinline__ void grid_barrier(unsigned phase) {
    __syncthreads();
    if (threadIdx.x == 0) {
        __threadfence();
        atomicAdd(&g_barrier, 1u);
        const unsigned target = phase * (unsigned)GRID_REC;
        while (*(volatile unsigned*)&g_barrier < target) { }
        __threadfence();
    }
    __syncthreads();
}

// ---------------- persistent GRU recurrence (batch-contiguous h) ----------------
template<int MYN>
__device__ __forceinline__ void kloop(float acc[2][3], const float* __restrict__ hT,
                                      int b,
                                      const float* __restrict__ wrow0,
                                      const float* __restrict__ wrow1) {
    const float* wr[2] = { wrow0, wrow1 };
#pragma unroll 4
    for (int k4 = 0; k4 < H / 4; k4++) {
        // coalesced: lane = b, consecutive addresses
        float h0 = hT[(size_t)(4 * k4 + 0) * B + b];
        float h1 = hT[(size_t)(4 * k4 + 1) * B + b];
        float h2 = hT[(size_t)(4 * k4 + 2) * B + b];
        float h3 = hT[(size_t)(4 * k4 + 3) * B + b];
#pragma unroll
        for (int c = 0; c < MYN; c++) {
#pragma unroll
            for (int g = 0; g < 3; g++) {
                float4 wv = *(const float4*)(wr[c] + (size_t)g * H + k4 * 4);
                acc[c][g] = fmaf(h0, wv.x, acc[c][g]);
                acc[c][g] = fmaf(h1, wv.y, acc[c][g]);
                acc[c][g] = fmaf(h2, wv.z, acc[c][g]);
                acc[c][g] = fmaf(h3, wv.w, acc[c][g]);
            }
        }
    }
}

__global__ __launch_bounds__(THR_REC) void gru_persistent(const float* __restrict__ Wh,
                                                          const float* __restrict__ bhb) {
    __shared__ float ws[15 * H];   // up to 5 cols * 3 gates
    const int tid = threadIdx.x;
    const int bh = blockIdx.x & 1;
    const int cb = blockIdx.x >> 1;
    const int j0 = cb * COLS_PER_BLK;
    const int ncols_blk = (cb == NCOLBLK - 1) ? (H - j0) : COLS_PER_BLK;  // 5 or 3
    const int nrows_blk = ncols_blk * 3;
    const int cg = tid >> 7;
    const int b  = bh * 128 + (tid & 127);

    for (int q = tid; q < nrows_blk * (H / 4); q += THR_REC) {
        int row = q / (H / 4);
        int kq  = q % (H / 4);
        int jj = row / 3, g = row % 3;
        *(float4*)&ws[(size_t)row * H + kq * 4] =
            *(const float4*)(Wh + (size_t)(g * H + j0 + jj) * H + kq * 4);
    }
    __syncthreads();

    int mycols[2]; int myn = 0;
    if (cg < ncols_blk) mycols[myn++] = cg;
    if (cg == 0 && ncols_blk == 5) mycols[myn++] = 4;
    if (myn == 0) mycols[0] = 0;
    if (myn < 2) mycols[1] = mycols[0];

    const float* wrow0 = ws + (size_t)(mycols[0] * 3) * H;
    const float* wrow1 = ws + (size_t)(mycols[1] * 3) * H;

    float bias[2][3];
#pragma unroll
    for (int c = 0; c < 2; c++)
#pragma unroll
        for (int g = 0; g < 3; g++)
            bias[c][g] = bhb[g * H + j0 + mycols[c]];

    for (int t = 0; t < T; t++) {
        float acc[2][3];
#pragma unroll
        for (int c = 0; c < 2; c++)
#pragma unroll
            for (int g = 0; g < 3; g++) acc[c][g] = bias[c][g];

        const float* hprevT = g_temporalT + (size_t)(t - 1) * H * B;
        if (t > 0 && myn > 0) {
            if (myn == 2) kloop<2>(acc, hprevT, b, wrow0, wrow1);
            else          kloop<1>(acc, hprevT, b, wrow0, wrow1);
        }

        if (myn > 0) {
            const float* xp = g_xprojT + (size_t)t * G3 * B;
            float* houtT = g_temporalT + (size_t)t * H * B;
#pragma unroll
            for (int c = 0; c < 2; c++) {
                if (c >= myn) break;
                int j = j0 + mycols[c];
                float gi_r = xp[((size_t)(0 * H + j)) * B + b];
                float gi_z = xp[((size_t)(1 * H + j)) * B + b];
                float gi_n = xp[((size_t)(2 * H + j)) * B + b];
                float r = 1.f / (1.f + expf(-(gi_r + acc[c][0])));
                float z = 1.f / (1.f + expf(-(gi_z + acc[c][1])));
                float n = tanhf(gi_n + r * acc[c][2]);
                float hp = (t > 0) ? hprevT[(size_t)j * B + b] : 0.f;
                houtT[(size_t)j * B + b] = (1.f - z) * n + z * hp;   // coalesced
            }
        }

        if (t < T - 1) grid_barrier((unsigned)(t + 1));
    }
}

// ---------------- Kernel 3: heads (coalesced, 192 blocks) ----------------
__global__ __launch_bounds__(128) void heads_kernel(const float* __restrict__ Wc,
                                                    const float* __restrict__ bc,
                                                    const float* __restrict__ Wf,
                                                    const float* __restrict__ bf,
                                                    float* __restrict__ out) {
    __shared__ float w[31 * H];
    const int t = blockIdx.x >> 1;
    const int half = blockIdx.x & 1;
    const int tid = threadIdx.x;
    const int b = half * 128 + tid;

    for (int q = tid; q < 31 * (H / 4); q += 128) {
        int row = q / (H / 4);
        int kq = q % (H / 4);
        const float* src = (row < 2) ? (Wc + (size_t)row * H) : (Wf + (size_t)(row - 2) * H);
        *(float4*)&w[(size_t)row * H + kq * 4] = *(const float4*)(src + kq * 4);
    }
    __syncthreads();

    float acc[31];
    acc[0] = bc[0];
    acc[1] = bc[1];
#pragma unroll
    for (int i = 0; i < NC; i++) acc[2 + i] = bf[i];

    const float* hT = g_temporalT + (size_t)t * H * B;
#pragma unroll 2
    for (int k4 = 0; k4 < H / 4; k4++) {
        float h0 = hT[(size_t)(4 * k4 + 0) * B + b];
        float h1 = hT[(size_t)(4 * k4 + 1) * B + b];
        float h2 = hT[(size_t)(4 * k4 + 2) * B + b];
        float h3 = hT[(size_t)(4 * k4 + 3) * B + b];
#pragma unroll
        for (int row = 0; row < 31; row++) {
            float4 wv = *(const float4*)&w[(size_t)row * H + k4 * 4];
            acc[row] = fmaf(h0, wv.x, acc[row]);
            acc[row] = fmaf(h1, wv.y, acc[row]);
            acc[row] = fmaf(h2, wv.z, acc[row]);
            acc[row] = fmaf(h3, wv.w, acc[row]);
        }
    }

    float l0 = acc[0], l1 = acc[1];
    float m = fmaxf(l0, l1);
    float e0 = expf(l0 - m), e1 = expf(l1 - m);
    float inv = 1.f / (e0 + e1);
    size_t idx = (size_t)b * T + t;
    g_scores[idx * 2 + 0] = e0 * inv;
    g_scores[idx * 2 + 1] = e1 * inv;

    float* fine = out + OUT_FINE_OFF + idx * NC;
#pragma unroll
    for (int i = 0; i < NC; i++) fine[i] = 1.f / (1.f + expf(-acc[2 + i]));
}

// ---------------- Kernel 4: NMS + decisions ----------------
__global__ void nms_kernel(float* __restrict__ out) {
    int idx = blockIdx.x * blockDim.x + threadIdx.x;
    if (idx >= B * T) return;
    int b = idx / T;
    int t = idx % T;
    const float* sb = g_scores + (size_t)b * T * 2;
    float s0 = sb[t * 2 + 0];
    float s1 = sb[t * 2 + 1];
    float wmin = INFINITY;
#pragma unroll
    for (int k = -2; k <= 2; k++) {
        int tt = t + k;
        if (tt >= 0 && tt < T) wmin = fminf(wmin, sb[tt * 2]);
    }
    bool keep = (s0 == wmin);
    float o0 = keep ? s0 : 0.f;
    float o1 = keep ? s1 : 0.f;
    out[idx] = (o1 > o0) ? 1.0f : 0.0f;
    out[OUT_NMS_OFF + (size_t)idx * 2 + 0] = o0;
    out[OUT_NMS_OFF + (size_t)idx * 2 + 1] = o1;
}

// ---------------- launch ----------------
extern "C" void kernel_launch(void* const* d_in, const int* in_sizes, int n_in,
                              void* d_out, int out_size) {
    const float* feat = (const float*)d_in[0];
    const float* Wi  = (const float*)d_in[2];
    const float* Wh  = (const float*)d_in[3];
    const float* bi  = (const float*)d_in[4];
    const float* bhb = (const float*)d_in[5];
    const float* Wc  = (const float*)d_in[6];
    const float* bc  = (const float*)d_in[7];
    const float* Wf  = (const float*)d_in[8];
    const float* bf  = (const float*)d_in[9];
    float* out = (float*)d_out;

    reset_barrier_kernel<<<1, 1>>>();

    dim3 g1((B * T) / BM, (G3 + BN - 1) / BN);
    xproj_gemm<<<g1, 256>>>(feat, Wi, bi);

    gru_persistent<<<GRID_REC, THR_REC>>>(Wh, bhb);

    heads_kernel<<<T * 2, 128>>>(Wc, bc, Wf, bf, out);
    nms_kernel<<<(B * T + 255) / 256, 256>>>(out);
}

// round 6
// speedup vs baseline: 1.4548x; 1.1898x over previous
#include <cuda_runtime.h>
#include <math.h>

// Problem constants
#define B 256
#define T 96
#define F 368
#define H 368
#define G3 1104          // 3*H
#define NC 29
#define OUT_NMS_OFF   (B*T)
#define OUT_FINE_OFF  (B*T + B*T*2)

// gru persistent config: 2 batch-halves x 62 col-blocks (6 cols each, last ragged)
#define NCB 62
#define GRID_REC 124
#define THR_REC 512

// ---------------- device scratch ----------------
__device__ float g_xprojT[(size_t)T * G3 * B];      // (t, g, b)  b contiguous
__device__ float g_temporalT[(size_t)T * H * B];    // (t, k, b)  b contiguous
__device__ float g_scores[(size_t)B * T * 2];
__device__ unsigned g_barrier;

// ---------------- f32x2 packed helpers ----------------
__device__ __forceinline__ unsigned long long fma2(unsigned long long a,
                                                   unsigned long long b,
                                                   unsigned long long c) {
    unsigned long long d;
    asm("fma.rn.f32x2 %0, %1, %2, %3;" : "=l"(d) : "l"(a), "l"(b), "l"(c));
    return d;
}
__device__ __forceinline__ unsigned long long add2(unsigned long long a,
                                                   unsigned long long b) {
    unsigned long long d;
    asm("add.rn.f32x2 %0, %1, %2;" : "=l"(d) : "l"(a), "l"(b));
    return d;
}
__device__ __forceinline__ unsigned long long packdup(float x) {
    unsigned long long r;
    unsigned u = __float_as_uint(x);
    asm("mov.b64 %0, {%1, %1};" : "=l"(r) : "r"(u));
    return r;
}
__device__ __forceinline__ float lo32(unsigned long long v) {
    return __uint_as_float((unsigned)v);
}
__device__ __forceinline__ float hi32(unsigned long long v) {
    return __uint_as_float((unsigned)(v >> 32));
}

// ---------------- Kernel 1: xproj = feat @ Wi^T + bi ----------------
// m = t*B + b tiling: block = (t, b-half 128) x 64 g.  Coalesced b-contiguous output.
#define BK 16
__global__ __launch_bounds__(256) void xproj_gemm(const float* __restrict__ feat,
                                                  const float* __restrict__ Wi,
                                                  const float* __restrict__ bi) {
    __shared__ float As[BK][128];
    __shared__ float Ws[BK][64];
    __shared__ float sC[128 * 65];     // [b-local][g] pad 65
    const int t  = blockIdx.x >> 1;
    const int b0 = (blockIdx.x & 1) * 128;
    const int bn = blockIdx.y * 64;
    const int tid = threadIdx.x;
    const int tx = tid % 16;           // g dir
    const int ty = tid / 16;           // b dir

    unsigned long long acc2[4][4];     // [b-pair][g]
#pragma unroll
    for (int i = 0; i < 4; i++)
#pragma unroll
        for (int j = 0; j < 4; j++) acc2[i][j] = 0ull;

    for (int kt = 0; kt < F; kt += BK) {
        // A tile: rows = b-local (strided rows of feat), 2 float4 per thread
#pragma unroll
        for (int l = 0; l < 2; l++) {
            int idx = tid + l * 256;
            int row = idx >> 2;
            int kq = idx & 3;
            float4 v = *(const float4*)(feat + ((size_t)(b0 + row) * T + t) * F + kt + kq * 4);
            As[kq * 4 + 0][row] = v.x;
            As[kq * 4 + 1][row] = v.y;
            As[kq * 4 + 2][row] = v.z;
            As[kq * 4 + 3][row] = v.w;
        }
        // W tile
        {
            int m = tid >> 2;
            int kq = tid & 3;
            int g = bn + m;
            float4 v = make_float4(0.f, 0.f, 0.f, 0.f);
            if (g < G3) v = *(const float4*)(Wi + (size_t)g * F + kt + kq * 4);
            Ws[kq * 4 + 0][m] = v.x;
            Ws[kq * 4 + 1][m] = v.y;
            Ws[kq * 4 + 2][m] = v.z;
            Ws[kq * 4 + 3][m] = v.w;
        }
        __syncthreads();
#pragma unroll
        for (int k = 0; k < BK; k++) {
            unsigned long long a2[4];
#pragma unroll
            for (int i = 0; i < 4; i++)
                a2[i] = *(const unsigned long long*)&As[k][ty * 8 + 2 * i];
            float4 wv = *(const float4*)&Ws[k][tx * 4];
            unsigned long long wd[4];
            wd[0] = packdup(wv.x); wd[1] = packdup(wv.y);
            wd[2] = packdup(wv.z); wd[3] = packdup(wv.w);
#pragma unroll
            for (int i = 0; i < 4; i++)
#pragma unroll
                for (int j = 0; j < 4; j++)
                    acc2[i][j] = fma2(a2[i], wd[j], acc2[i][j]);
        }
        __syncthreads();
    }

    // stage to SMEM [b][g] (pad 65 -> low conflict), then coalesced write
#pragma unroll
    for (int i = 0; i < 4; i++) {
        int r0 = ty * 8 + 2 * i;
#pragma unroll
        for (int j = 0; j < 4; j++) {
            int g = tx * 4 + j;
            sC[(size_t)r0 * 65 + g]       = lo32(acc2[i][j]);
            sC[(size_t)(r0 + 1) * 65 + g] = hi32(acc2[i][j]);
        }
    }
    __syncthreads();
    // 64 g-rows x 128 b floats: scalar coalesced STG
    for (int q = tid; q < 64 * 128; q += 256) {
        int g = q >> 7;
        int b = q & 127;
        int gg = bn + g;
        if (gg < G3) {
            float v = sC[(size_t)b * 65 + g] + __ldg(bi + gg);
            g_xprojT[((size_t)t * G3 + gg) * B + b0 + b] = v;
        }
    }
}

// ---------------- barrier reset ----------------
__global__ void reset_barrier_kernel() { g_barrier = 0u; }

__device__ __forceinline__ void grid_barrier(unsigned phase) {
    __syncthreads();
    if (threadIdx.x == 0) {
        __threadfence();
        atomicAdd(&g_barrier, 1u);
        const unsigned target = phase * (unsigned)GRID_REC;
        while (*(volatile unsigned*)&g_barrier < target) { }
        __threadfence();
    }
    __syncthreads();
}

// ---------------- persistent GRU recurrence ----------------
// block = (b-half 128) x (6 cols = 3 pairs); cg = tid>>7 = k-quarter (92 k each).
// Weights pre-paired in SMEM; f32x2 FMA; cross-cg reduction in SMEM.
__global__ __launch_bounds__(THR_REC) void gru_persistent(const float* __restrict__ Wh,
                                                          const float* __restrict__ bhb) {
    __shared__ float wsp[9 * H * 2];             // [(p*3+g)*H + k] pairs (lo,hi)  26.5 KB
    __shared__ unsigned long long red[THR_REC * 9];  // partials  36.9 KB
    const int tid = threadIdx.x;
    const int bh = blockIdx.x & 1;
    const int cb = blockIdx.x >> 1;              // 0..61
    const int j0 = cb * 6;
    const int cg = tid >> 7;                     // k-quarter
    const int b  = bh * 128 + (tid & 127);
    const int k0 = cg * 92;

    // Load paired weights once: wsp[(row*H + k)*2 + {0,1}] = Wh rows (j0+2p, j0+2p+1), gate g
    for (int q = tid; q < 9 * H; q += THR_REC) {
        int row = q / H;                          // p*3+g
        int k   = q % H;
        int p = row / 3, g = row % 3;
        int ja = j0 + 2 * p, jb = ja + 1;
        float lo = (ja < H) ? Wh[((size_t)g * H + ja) * H + k] : 0.f;
        float hi = (jb < H) ? Wh[((size_t)g * H + jb) * H + k] : 0.f;
        wsp[(size_t)q * 2 + 0] = lo;
        wsp[(size_t)q * 2 + 1] = hi;
    }
    __syncthreads();

    for (int t = 0; t < T; t++) {
        unsigned long long acc[9];
#pragma unroll
        for (int r = 0; r < 9; r++) acc[r] = 0ull;

        const float* hprevT = g_temporalT + (size_t)(t - 1) * H * B;
        if (t > 0) {
#pragma unroll 1
            for (int k4 = 0; k4 < 23; k4++) {
                int k = k0 + k4 * 4;
                float h0 = hprevT[(size_t)(k + 0) * B + b];
                float h1 = hprevT[(size_t)(k + 1) * B + b];
                float h2 = hprevT[(size_t)(k + 2) * B + b];
                float h3 = hprevT[(size_t)(k + 3) * B + b];
                unsigned long long hd0 = packdup(h0), hd1 = packdup(h1);
                unsigned long long hd2 = packdup(h2), hd3 = packdup(h3);
#pragma unroll
                for (int r = 0; r < 9; r++) {
                    const float* wp = wsp + ((size_t)r * H + k) * 2;
                    ulonglong2 wA = *(const ulonglong2*)(wp);
                    ulonglong2 wB = *(const ulonglong2*)(wp + 4);
                    acc[r] = fma2(hd0, wA.x, acc[r]);
                    acc[r] = fma2(hd1, wA.y, acc[r]);
                    acc[r] = fma2(hd2, wB.x, acc[r]);
                    acc[r] = fma2(hd3, wB.y, acc[r]);
                }
            }
        }

        // store partials
        {
            unsigned long long* dst = red + (size_t)tid * 9;
#pragma unroll
            for (int r = 0; r < 9; r++) dst[r] = acc[r];
        }
        __syncthreads();

        // reduce + gate math: threads 0..383: p = tid>>7, b2 = tid&127
        if (tid < 384) {
            int p  = tid >> 7;
            int b2 = tid & 127;
            int bb = bh * 128 + b2;
            int ja = j0 + 2 * p;
            if (ja < H) {
                int jb = ja + 1;    // jb < H always (H even, ja even)
                unsigned long long s[3];
#pragma unroll
                for (int g = 0; g < 3; g++) {
                    int r = p * 3 + g;
                    unsigned long long v = red[((size_t)0 * 128 + b2) * 9 + r];
                    v = add2(v, red[((size_t)1 * 128 + b2) * 9 + r]);
                    v = add2(v, red[((size_t)2 * 128 + b2) * 9 + r]);
                    v = add2(v, red[((size_t)3 * 128 + b2) * 9 + r]);
                    s[g] = v;
                }
                const float* xp = g_xprojT + (size_t)t * G3 * B;
                float* houtT = g_temporalT + (size_t)t * H * B;
#pragma unroll
                for (int c = 0; c < 2; c++) {
                    int j = (c == 0) ? ja : jb;
                    float gh_r = ((c == 0) ? lo32(s[0]) : hi32(s[0])) + bhb[0 * H + j];
                    float gh_z = ((c == 0) ? lo32(s[1]) : hi32(s[1])) + bhb[1 * H + j];
                    float gh_n = ((c == 0) ? lo32(s[2]) : hi32(s[2])) + bhb[2 * H + j];
                    float gi_r = xp[((size_t)(0 * H + j)) * B + bb];
                    float gi_z = xp[((size_t)(1 * H + j)) * B + bb];
                    float gi_n = xp[((size_t)(2 * H + j)) * B + bb];
                    float r = 1.f / (1.f + expf(-(gi_r + gh_r)));
                    float z = 1.f / (1.f + expf(-(gi_z + gh_z)));
                    float n = tanhf(gi_n + r * gh_n);
                    float hp = (t > 0) ? hprevT[(size_t)j * B + bb] : 0.f;
                    houtT[(size_t)j * B + bb] = (1.f - z) * n + z * hp;
                }
            }
        }

        if (t < T - 1) grid_barrier((unsigned)(t + 1));
    }
}

// ---------------- Kernel 3: heads (f32x2 paired) ----------------
__global__ __launch_bounds__(128) void heads_kernel(const float* __restrict__ Wc,
                                                    const float* __restrict__ bc,
                                                    const float* __restrict__ Wf,
                                                    const float* __restrict__ bf,
                                                    float* __restrict__ out) {
    __shared__ float wp[15 * H * 2];   // row-pairs (2r, 2r+1) interleaved  44.2 KB
    __shared__ float ws30[H];          // last row (index 30 = Wf[28])
    const int t = blockIdx.x >> 1;
    const int half = blockIdx.x & 1;
    const int tid = threadIdx.x;
    const int b = half * 128 + tid;

    for (int q = tid; q < 15 * H; q += 128) {
        int r = q / H;
        int k = q % H;
        int ra = 2 * r, rb = 2 * r + 1;
        float lo = (ra < 2) ? Wc[(size_t)ra * H + k] : Wf[(size_t)(ra - 2) * H + k];
        float hi = (rb < 2) ? Wc[(size_t)rb * H + k] : Wf[(size_t)(rb - 2) * H + k];
        wp[(size_t)q * 2 + 0] = lo;
        wp[(size_t)q * 2 + 1] = hi;
    }
    for (int k = tid; k < H; k += 128) ws30[k] = Wf[(size_t)28 * H + k];
    __syncthreads();

    unsigned long long acc[15];
#pragma unroll
    for (int r = 0; r < 15; r++) acc[r] = 0ull;
    float acc30 = 0.f;

    const float* hT = g_temporalT + (size_t)t * H * B;
#pragma unroll 1
    for (int k4 = 0; k4 < H / 4; k4++) {
        int k = k4 * 4;
        float h0 = hT[(size_t)(k + 0) * B + b];
        float h1 = hT[(size_t)(k + 1) * B + b];
        float h2 = hT[(size_t)(k + 2) * B + b];
        float h3 = hT[(size_t)(k + 3) * B + b];
        unsigned long long hd0 = packdup(h0), hd1 = packdup(h1);
        unsigned long long hd2 = packdup(h2), hd3 = packdup(h3);
#pragma unroll
        for (int r = 0; r < 15; r++) {
            const float* p = wp + ((size_t)r * H + k) * 2;
            ulonglong2 wA = *(const ulonglong2*)(p);
            ulonglong2 wB = *(const ulonglong2*)(p + 4);
            acc[r] = fma2(hd0, wA.x, acc[r]);
            acc[r] = fma2(hd1, wA.y, acc[r]);
            acc[r] = fma2(hd2, wB.x, acc[r]);
            acc[r] = fma2(hd3, wB.y, acc[r]);
        }
        float4 w30 = *(const float4*)&ws30[k];
        acc30 = fmaf(h0, w30.x, acc30);
        acc30 = fmaf(h1, w30.y, acc30);
        acc30 = fmaf(h2, w30.z, acc30);
        acc30 = fmaf(h3, w30.w, acc30);
    }

    float logit[31];
#pragma unroll
    for (int r = 0; r < 15; r++) {
        logit[2 * r]     = lo32(acc[r]);
        logit[2 * r + 1] = hi32(acc[r]);
    }
    logit[30] = acc30;
    logit[0] += bc[0];
    logit[1] += bc[1];
#pragma unroll
    for (int i = 0; i < NC; i++) logit[2 + i] += bf[i];

    float l0 = logit[0], l1 = logit[1];
    float m = fmaxf(l0, l1);
    float e0 = expf(l0 - m), e1 = expf(l1 - m);
    float inv = 1.f / (e0 + e1);
    size_t idx = (size_t)b * T + t;
    g_scores[idx * 2 + 0] = e0 * inv;
    g_scores[idx * 2 + 1] = e1 * inv;

    float* fine = out + OUT_FINE_OFF + idx * NC;
#pragma unroll
    for (int i = 0; i < NC; i++) fine[i] = 1.f / (1.f + expf(-logit[2 + i]));
}

// ---------------- Kernel 4: NMS + decisions ----------------
__global__ void nms_kernel(float* __restrict__ out) {
    int idx = blockIdx.x * blockDim.x + threadIdx.x;
    if (idx >= B * T) return;
    int b = idx / T;
    int t = idx % T;
    const float* sb = g_scores + (size_t)b * T * 2;
    float s0 = sb[t * 2 + 0];
    float s1 = sb[t * 2 + 1];
    float wmin = INFINITY;
#pragma unroll
    for (int k = -2; k <= 2; k++) {
        int tt = t + k;
        if (tt >= 0 && tt < T) wmin = fminf(wmin, sb[tt * 2]);
    }
    bool keep = (s0 == wmin);
    float o0 = keep ? s0 : 0.f;
    float o1 = keep ? s1 : 0.f;
    out[idx] = (o1 > o0) ? 1.0f : 0.0f;
    out[OUT_NMS_OFF + (size_t)idx * 2 + 0] = o0;
    out[OUT_NMS_OFF + (size_t)idx * 2 + 1] = o1;
}

// ---------------- launch ----------------
extern "C" void kernel_launch(void* const* d_in, const int* in_sizes, int n_in,
                              void* d_out, int out_size) {
    const float* feat = (const float*)d_in[0];
    const float* Wi  = (const float*)d_in[2];
    const float* Wh  = (const float*)d_in[3];
    const float* bi  = (const float*)d_in[4];
    const float* bhb = (const float*)d_in[5];
    const float* Wc  = (const float*)d_in[6];
    const float* bc  = (const float*)d_in[7];
    const float* Wf  = (const float*)d_in[8];
    const float* bf  = (const float*)d_in[9];
    float* out = (float*)d_out;

    reset_barrier_kernel<<<1, 1>>>();

    dim3 g1(T * 2, (G3 + 63) / 64);   // 192 x 18
    xproj_gemm<<<g1, 256>>>(feat, Wi, bi);

    gru_persistent<<<GRID_REC, THR_REC>>>(Wh, bhb);

    heads_kernel<<<T * 2, 128>>>(Wc, bc, Wf, bf, out);
    nms_kernel<<<(B * T + 255) / 256, 256>>>(out);
}

// round 7
// speedup vs baseline: 1.8336x; 1.2604x over previous
#include <cuda_runtime.h>
#include <math.h>

// Problem constants
#define B 256
#define T 96
#define F 368
#define H 368
#define G3 1104          // 3*H
#define NC 29
#define OUT_NMS_OFF   (B*T)
#define OUT_FINE_OFF  (B*T + B*T*2)

// gru persistent config: 2 batch-halves x 62 col-blocks (6 cols each, last ragged)
#define NCB 62
#define GRID_REC 124
#define THR_REC 512

// ---------------- device scratch ----------------
__device__ float g_xprojT[(size_t)T * G3 * B];      // (t, g, b)  b contiguous
__device__ float g_temporalT[(size_t)T * H * B];    // (t, k, b)  b contiguous
__device__ float g_scores[(size_t)B * T * 2];
__device__ unsigned g_arrive[2][NCB * 32];          // per-block arrival slot, 128B apart
__device__ unsigned g_release[64];                  // [bh*32]

// ---------------- f32x2 packed helpers ----------------
__device__ __forceinline__ unsigned long long fma2(unsigned long long a,
                                                   unsigned long long b,
                                                   unsigned long long c) {
    unsigned long long d;
    asm("fma.rn.f32x2 %0, %1, %2, %3;" : "=l"(d) : "l"(a), "l"(b), "l"(c));
    return d;
}
__device__ __forceinline__ unsigned long long add2(unsigned long long a,
                                                   unsigned long long b) {
    unsigned long long d;
    asm("add.rn.f32x2 %0, %1, %2;" : "=l"(d) : "l"(a), "l"(b));
    return d;
}
__device__ __forceinline__ unsigned long long packdup(float x) {
    unsigned long long r;
    unsigned u = __float_as_uint(x);
    asm("mov.b64 %0, {%1, %1};" : "=l"(r) : "r"(u));
    return r;
}
__device__ __forceinline__ float lo32(unsigned long long v) {
    return __uint_as_float((unsigned)v);
}
__device__ __forceinline__ float hi32(unsigned long long v) {
    return __uint_as_float((unsigned)(v >> 32));
}
__device__ __forceinline__ float fsigmoid(float x) {
    return 1.f / (1.f + __expf(-x));
}
__device__ __forceinline__ float ftanh(float x) {
    float ex = __expf(2.f * x);
    return 1.f - 2.f / (ex + 1.f);
}

// ---------------- Kernel 1: xproj = feat @ Wi^T + bi ----------------
#define BK 16
__global__ __launch_bounds__(256) void xproj_gemm(const float* __restrict__ feat,
                                                  const float* __restrict__ Wi,
                                                  const float* __restrict__ bi) {
    __shared__ float As[BK][128];
    __shared__ float Ws[BK][64];
    __shared__ float sC[128 * 65];
    const int t  = blockIdx.x >> 1;
    const int b0 = (blockIdx.x & 1) * 128;
    const int bn = blockIdx.y * 64;
    const int tid = threadIdx.x;
    const int tx = tid % 16;
    const int ty = tid / 16;

    unsigned long long acc2[4][4];
#pragma unroll
    for (int i = 0; i < 4; i++)
#pragma unroll
        for (int j = 0; j < 4; j++) acc2[i][j] = 0ull;

    for (int kt = 0; kt < F; kt += BK) {
#pragma unroll
        for (int l = 0; l < 2; l++) {
            int idx = tid + l * 256;
            int row = idx >> 2;
            int kq = idx & 3;
            float4 v = *(const float4*)(feat + ((size_t)(b0 + row) * T + t) * F + kt + kq * 4);
            As[kq * 4 + 0][row] = v.x;
            As[kq * 4 + 1][row] = v.y;
            As[kq * 4 + 2][row] = v.z;
            As[kq * 4 + 3][row] = v.w;
        }
        {
            int m = tid >> 2;
            int kq = tid & 3;
            int g = bn + m;
            float4 v = make_float4(0.f, 0.f, 0.f, 0.f);
            if (g < G3) v = *(const float4*)(Wi + (size_t)g * F + kt + kq * 4);
            Ws[kq * 4 + 0][m] = v.x;
            Ws[kq * 4 + 1][m] = v.y;
            Ws[kq * 4 + 2][m] = v.z;
            Ws[kq * 4 + 3][m] = v.w;
        }
        __syncthreads();
#pragma unroll
        for (int k = 0; k < BK; k++) {
            unsigned long long a2[4];
#pragma unroll
            for (int i = 0; i < 4; i++)
                a2[i] = *(const unsigned long long*)&As[k][ty * 8 + 2 * i];
            float4 wv = *(const float4*)&Ws[k][tx * 4];
            unsigned long long wd[4];
            wd[0] = packdup(wv.x); wd[1] = packdup(wv.y);
            wd[2] = packdup(wv.z); wd[3] = packdup(wv.w);
#pragma unroll
            for (int i = 0; i < 4; i++)
#pragma unroll
                for (int j = 0; j < 4; j++)
                    acc2[i][j] = fma2(a2[i], wd[j], acc2[i][j]);
        }
        __syncthreads();
    }

#pragma unroll
    for (int i = 0; i < 4; i++) {
        int r0 = ty * 8 + 2 * i;
#pragma unroll
        for (int j = 0; j < 4; j++) {
            int g = tx * 4 + j;
            sC[(size_t)r0 * 65 + g]       = lo32(acc2[i][j]);
            sC[(size_t)(r0 + 1) * 65 + g] = hi32(acc2[i][j]);
        }
    }
    __syncthreads();
    for (int q = tid; q < 64 * 128; q += 256) {
        int g = q >> 7;
        int b = q & 127;
        int gg = bn + g;
        if (gg < G3) {
            float v = sC[(size_t)b * 65 + g] + __ldg(bi + gg);
            g_xprojT[((size_t)t * G3 + gg) * B + b0 + b] = v;
        }
    }
}

// ---------------- barrier reset ----------------
__global__ void reset_barrier_kernel() {
    int tid = threadIdx.x;
    for (int q = tid; q < 2 * NCB * 32; q += 256) {
        ((unsigned*)g_arrive)[q] = 0u;
    }
    if (tid < 64) g_release[tid] = 0u;
}

// ---------------- per-half grid barrier (no atomics) ----------------
__device__ __forceinline__ void half_barrier(int bh, int cb, unsigned s) {
    __syncthreads();
    if (threadIdx.x == 0) {
        __threadfence();
        *(volatile unsigned*)&g_arrive[bh][cb * 32] = s;
    }
    if (cb == 0 && threadIdx.x < 31) {
        int i0 = threadIdx.x * 2;
        int i1 = i0 + 1;
        bool done = false;
        while (!done) {
            unsigned a = *(volatile unsigned*)&g_arrive[bh][i0 * 32];
            unsigned c = (i1 < NCB) ? *(volatile unsigned*)&g_arrive[bh][i1 * 32] : s;
            done = __all_sync(0x7fffffffu, (a >= s) && (c >= s));
        }
        if (threadIdx.x == 0) {
            __threadfence();
            *(volatile unsigned*)&g_release[bh * 32] = s;
        }
    }
    if (threadIdx.x == 0) {
        while (*(volatile unsigned*)&g_release[bh * 32] < s) { }
        __threadfence();
    }
    __syncthreads();
}

// ---------------- persistent GRU recurrence ----------------
__global__ __launch_bounds__(THR_REC) void gru_persistent(const float* __restrict__ Wh,
                                                          const float* __restrict__ bhb) {
    __shared__ float wsp[9 * H * 2];                 // paired weights  26.5 KB
    __shared__ unsigned long long red[THR_REC * 9];  // partials        36.9 KB
    const int tid = threadIdx.x;
    const int bh = blockIdx.x & 1;
    const int cb = blockIdx.x >> 1;              // 0..61
    const int j0 = cb * 6;
    const int cg = tid >> 7;                     // k-quarter
    const int b  = bh * 128 + (tid & 127);
    const int k0 = cg * 92;

    // gate-role mapping (threads 0..383)
    const int gp  = tid >> 7;                    // pair index 0..2 (only tid<384)
    const int gb2 = tid & 127;
    const int gbb = bh * 128 + gb2;
    const int gja = j0 + 2 * gp;
    const bool gate = (tid < 384) && (gja < H);

    // Load paired weights once
    for (int q = tid; q < 9 * H; q += THR_REC) {
        int row = q / H;
        int k   = q % H;
        int p = row / 3, g = row % 3;
        int ja = j0 + 2 * p, jb = ja + 1;
        float lo = (ja < H) ? Wh[((size_t)g * H + ja) * H + k] : 0.f;
        float hi = (jb < H) ? Wh[((size_t)g * H + jb) * H + k] : 0.f;
        wsp[(size_t)q * 2 + 0] = lo;
        wsp[(size_t)q * 2 + 1] = hi;
    }
    // gate biases resident in regs
    float gbias[2][3];
    if (gate) {
#pragma unroll
        for (int c = 0; c < 2; c++)
#pragma unroll
            for (int g = 0; g < 3; g++)
                gbias[c][g] = bhb[g * H + gja + c];
    }
    __syncthreads();

    for (int t = 0; t < T; t++) {
        const float* hprevT = g_temporalT + (size_t)(t - 1) * H * B;

        // ---- prefetch gi (xproj) + hp: independent of h[t-1] compute ----
        float gi[2][3];
        float hp[2];
        if (gate) {
            const float* xp = g_xprojT + (size_t)t * G3 * B;
#pragma unroll
            for (int c = 0; c < 2; c++) {
                int j = gja + c;
                gi[c][0] = xp[((size_t)(0 * H + j)) * B + gbb];
                gi[c][1] = xp[((size_t)(1 * H + j)) * B + gbb];
                gi[c][2] = xp[((size_t)(2 * H + j)) * B + gbb];
                hp[c] = (t > 0) ? hprevT[(size_t)j * B + gbb] : 0.f;
            }
        }

        // ---- main matvec ----
        unsigned long long acc[9];
#pragma unroll
        for (int r = 0; r < 9; r++) acc[r] = 0ull;

        if (t > 0) {
#pragma unroll 1
            for (int k4 = 0; k4 < 23; k4++) {
                int k = k0 + k4 * 4;
                float h0 = hprevT[(size_t)(k + 0) * B + b];
                float h1 = hprevT[(size_t)(k + 1) * B + b];
                float h2 = hprevT[(size_t)(k + 2) * B + b];
                float h3 = hprevT[(size_t)(k + 3) * B + b];
                unsigned long long hd0 = packdup(h0), hd1 = packdup(h1);
                unsigned long long hd2 = packdup(h2), hd3 = packdup(h3);
#pragma unroll
                for (int r = 0; r < 9; r++) {
                    const float* wp = wsp + ((size_t)r * H + k) * 2;
                    ulonglong2 wA = *(const ulonglong2*)(wp);
                    ulonglong2 wB = *(const ulonglong2*)(wp + 4);
                    acc[r] = fma2(hd0, wA.x, acc[r]);
                    acc[r] = fma2(hd1, wA.y, acc[r]);
                    acc[r] = fma2(hd2, wB.x, acc[r]);
                    acc[r] = fma2(hd3, wB.y, acc[r]);
                }
            }
        }

        {
            unsigned long long* dst = red + (size_t)tid * 9;
#pragma unroll
            for (int r = 0; r < 9; r++) dst[r] = acc[r];
        }
        __syncthreads();

        // ---- reduce + gates (prefetched gi/hp already in regs) ----
        if (gate) {
            unsigned long long s[3];
#pragma unroll
            for (int g = 0; g < 3; g++) {
                int r = gp * 3 + g;
                unsigned long long v = red[((size_t)0 * 128 + gb2) * 9 + r];
                v = add2(v, red[((size_t)1 * 128 + gb2) * 9 + r]);
                v = add2(v, red[((size_t)2 * 128 + gb2) * 9 + r]);
                v = add2(v, red[((size_t)3 * 128 + gb2) * 9 + r]);
                s[g] = v;
            }
            float* houtT = g_temporalT + (size_t)t * H * B;
#pragma unroll
            for (int c = 0; c < 2; c++) {
                int j = gja + c;
                float gh_r = ((c == 0) ? lo32(s[0]) : hi32(s[0])) + gbias[c][0];
                float gh_z = ((c == 0) ? lo32(s[1]) : hi32(s[1])) + gbias[c][1];
                float gh_n = ((c == 0) ? lo32(s[2]) : hi32(s[2])) + gbias[c][2];
                float r = fsigmoid(gi[c][0] + gh_r);
                float z = fsigmoid(gi[c][1] + gh_z);
                float n = ftanh(gi[c][2] + r * gh_n);
                houtT[(size_t)j * B + gbb] = (1.f - z) * n + z * hp[c];
            }
        }

        if (t < T - 1) half_barrier(bh, cb, (unsigned)(t + 1));
    }
}

// ---------------- Kernel 3: heads (256 threads, fast math) ----------------
__global__ __launch_bounds__(256) void heads_kernel(const float* __restrict__ Wc,
                                                    const float* __restrict__ bc,
                                                    const float* __restrict__ Wf,
                                                    const float* __restrict__ bf,
                                                    float* __restrict__ out) {
    __shared__ float wp[15 * H * 2];   // row pairs interleaved
    __shared__ float ws30[H];
    const int t = blockIdx.x;
    const int tid = threadIdx.x;
    const int b = tid;

    for (int q = tid; q < 15 * H; q += 256) {
        int r = q / H;
        int k = q % H;
        int ra = 2 * r, rb = 2 * r + 1;
        float lo = (ra < 2) ? Wc[(size_t)ra * H + k] : Wf[(size_t)(ra - 2) * H + k];
        float hi = (rb < 2) ? Wc[(size_t)rb * H + k] : Wf[(size_t)(rb - 2) * H + k];
        wp[(size_t)q * 2 + 0] = lo;
        wp[(size_t)q * 2 + 1] = hi;
    }
    for (int k = tid; k < H; k += 256) ws30[k] = Wf[(size_t)28 * H + k];
    __syncthreads();

    unsigned long long acc[15];
#pragma unroll
    for (int r = 0; r < 15; r++) acc[r] = 0ull;
    float acc30 = 0.f;

    const float* hT = g_temporalT + (size_t)t * H * B;
#pragma unroll 1
    for (int k4 = 0; k4 < H / 4; k4++) {
        int k = k4 * 4;
        float h0 = hT[(size_t)(k + 0) * B + b];
        float h1 = hT[(size_t)(k + 1) * B + b];
        float h2 = hT[(size_t)(k + 2) * B + b];
        float h3 = hT[(size_t)(k + 3) * B + b];
        unsigned long long hd0 = packdup(h0), hd1 = packdup(h1);
        unsigned long long hd2 = packdup(h2), hd3 = packdup(h3);
#pragma unroll
        for (int r = 0; r < 15; r++) {
            const float* p = wp + ((size_t)r * H + k) * 2;
            ulonglong2 wA = *(const ulonglong2*)(p);
            ulonglong2 wB = *(const ulonglong2*)(p + 4);
            acc[r] = fma2(hd0, wA.x, acc[r]);
            acc[r] = fma2(hd1, wA.y, acc[r]);
            acc[r] = fma2(hd2, wB.x, acc[r]);
            acc[r] = fma2(hd3, wB.y, acc[r]);
        }
        float4 w30 = *(const float4*)&ws30[k];
        acc30 = fmaf(h0, w30.x, acc30);
        acc30 = fmaf(h1, w30.y, acc30);
        acc30 = fmaf(h2, w30.z, acc30);
        acc30 = fmaf(h3, w30.w, acc30);
    }

    float logit[31];
#pragma unroll
    for (int r = 0; r < 15; r++) {
        logit[2 * r]     = lo32(acc[r]);
        logit[2 * r + 1] = hi32(acc[r]);
    }
    logit[30] = acc30;
    logit[0] += bc[0];
    logit[1] += bc[1];
#pragma unroll
    for (int i = 0; i < NC; i++) logit[2 + i] += bf[i];

    float l0 = logit[0], l1 = logit[1];
    float m = fmaxf(l0, l1);
    float e0 = __expf(l0 - m), e1 = __expf(l1 - m);
    float inv = 1.f / (e0 + e1);
    size_t idx = (size_t)b * T + t;
    g_scores[idx * 2 + 0] = e0 * inv;
    g_scores[idx * 2 + 1] = e1 * inv;

    float* fine = out + OUT_FINE_OFF + idx * NC;
#pragma unroll
    for (int i = 0; i < NC; i++) fine[i] = fsigmoid(logit[2 + i]);
}

// ---------------- Kernel 4: NMS + decisions ----------------
__global__ void nms_kernel(float* __restrict__ out) {
    int idx = blockIdx.x * blockDim.x + threadIdx.x;
    if (idx >= B * T) return;
    int b = idx / T;
    int t = idx % T;
    const float* sb = g_scores + (size_t)b * T * 2;
    float s0 = sb[t * 2 + 0];
    float s1 = sb[t * 2 + 1];
    float wmin = INFINITY;
#pragma unroll
    for (int k = -2; k <= 2; k++) {
        int tt = t + k;
        if (tt >= 0 && tt < T) wmin = fminf(wmin, sb[tt * 2]);
    }
    bool keep = (s0 == wmin);
    float o0 = keep ? s0 : 0.f;
    float o1 = keep ? s1 : 0.f;
    out[idx] = (o1 > o0) ? 1.0f : 0.0f;
    out[OUT_NMS_OFF + (size_t)idx * 2 + 0] = o0;
    out[OUT_NMS_OFF + (size_t)idx * 2 + 1] = o1;
}

// ---------------- launch ----------------
extern "C" void kernel_launch(void* const* d_in, const int* in_sizes, int n_in,
                              void* d_out, int out_size) {
    const float* feat = (const float*)d_in[0];
    const float* Wi  = (const float*)d_in[2];
    const float* Wh  = (const float*)d_in[3];
    const float* bi  = (const float*)d_in[4];
    const float* bhb = (const float*)d_in[5];
    const float* Wc  = (const float*)d_in[6];
    const float* bc  = (const float*)d_in[7];
    const float* Wf  = (const float*)d_in[8];
    const float* bf  = (const float*)d_in[9];
    float* out = (float*)d_out;

    reset_barrier_kernel<<<1, 256>>>();

    dim3 g1(T * 2, (G3 + 63) / 64);   // 192 x 18
    xproj_gemm<<<g1, 256>>>(feat, Wi, bi);

    gru_persistent<<<GRID_REC, THR_REC>>>(Wh, bhb);

    heads_kernel<<<T, 256>>>(Wc, bc, Wf, bf, out);
    nms_kernel<<<(B * T + 255) / 256, 256>>>(out);
}